// round 1
// baseline (speedup 1.0000x reference)
#include <cuda_runtime.h>
#include <math.h>

#define TLEN 8388608
#define NFFT 512
#define HOP  128
#define NK   257
#define NF   65537
#define XP   (TLEN + NFFT)   /* 8389120 padded length */
#define PAD  256

// ---------------- device scratch (no allocations allowed) ----------------
__device__ float2 g_spec[(size_t)NF * NK];   // complex STFT, [frame][bin]
__device__ float  g_gain[(size_t)NF * NK];   // Wiener gain,  [frame][bin]
__device__ float  g_y[XP];                   // overlap-add accumulator

// ---------------- shared-memory 512-pt complex FFT (radix-2 DIT) --------
// Input must be placed in bit-reversed order. dir = -1 forward, +1 inverse.
__device__ __forceinline__ void fft512_stages(float2* sh, int tid, float dir)
{
#pragma unroll
    for (int len = 2; len <= 512; len <<= 1) {
        int half = len >> 1;
        int pos  = tid & (half - 1);
        int i0   = ((tid - pos) << 1) + pos;   // group*len + pos
        int i1   = i0 + half;
        float s, c;
        sincospif(dir * 2.0f * (float)pos / (float)len, &s, &c);
        float2 u = sh[i0], v = sh[i1];
        float tr = v.x * c - v.y * s;
        float ti = v.x * s + v.y * c;
        sh[i0] = make_float2(u.x + tr, u.y + ti);
        sh[i1] = make_float2(u.x - tr, u.y - ti);
        __syncthreads();
    }
}

__device__ __forceinline__ float hann_win(int j)
{
    // periodic Hann: 0.5*(1 - cos(2*pi*j/512)) = 0.5*(1 - cospi(j/256))
    return 0.5f * (1.0f - cospif((float)j * (1.0f / 256.0f)));
}

// ---------------- kernel 0: zero the OLA accumulator ---------------------
__global__ void zero_y_kernel()
{
    int i = blockIdx.x * blockDim.x + threadIdx.x;
    if (i < XP) g_y[i] = 0.0f;
}

// ---------------- kernel 1: STFT ----------------------------------------
// one block (256 threads) per frame; reflect padding + Hann window + FFT.
__global__ void stft_kernel(const float* __restrict__ x)
{
    __shared__ float2 sh[512];
    int f   = blockIdx.x;
    int tid = threadIdx.x;
    long start = (long)f * HOP;

#pragma unroll
    for (int r = 0; r < 2; r++) {
        int  j  = tid + r * 256;
        long gi = start + j;
        long i  = gi - PAD;              // reflect pad of pad=256 on both ends
        if (i < 0)      i = -i;
        if (i >= TLEN)  i = 2L * TLEN - 2 - i;
        float val = x[i] * hann_win(j);
        sh[__brev((unsigned)j) >> 23] = make_float2(val, 0.0f);
    }
    __syncthreads();

    fft512_stages(sh, tid, -1.0f);       // forward

    size_t base = (size_t)f * NK;
    g_spec[base + tid] = sh[tid];        // bins 0..255
    if (tid == 0) g_spec[base + 256] = sh[256];
}

// ---------------- kernel 2: running-max scan + Wiener gain ---------------
// one block per frequency bin k; chunked parallel max-scan over frames.
// rmax_t = d^t * prefmax_s( m_s * d^{-s} ), chunk-rescaled to stay in range.
__global__ void scan_kernel()
{
    const int k    = blockIdx.x;         // 0..256
    const int tid  = threadIdx.x;        // 0..255
    const int lane = tid & 31;
    const int wid  = tid >> 5;

    __shared__ float wmax[8];
    __shared__ float sh_carry;

    const float LND   = 1.0005003335835335e-3f;  // -ln(0.999)
    const float DECAY = 0.999f;
    const float dinv  = expf((float)tid * LND);  // d^{-tid}
    const float dpow  = expf(-(float)tid * LND); // d^{+tid}

    float carry = 0.0f;
    const int NCH = (NF + 255) / 256;    // 257 chunks

    // prefetch chunk 0
    float2 s_cur = make_float2(0.f, 0.f);
    {
        int f = tid;
        if (f < NF) s_cur = g_spec[(size_t)f * NK + k];
    }

    for (int c = 0; c < NCH; c++) {
        int f = c * 256 + tid;
        float m = 0.0f, v = 0.0f;
        if (f < NF) {
            m = sqrtf(s_cur.x * s_cur.x + s_cur.y * s_cur.y);
            v = m * dinv;
        }
        // prefetch next chunk (overlaps the scan below)
        if (c + 1 < NCH) {
            int fn = (c + 1) * 256 + tid;
            if (fn < NF) s_cur = g_spec[(size_t)fn * NK + k];
        }

        // inclusive block-wide max scan of v
        float p = v;
#pragma unroll
        for (int o = 1; o < 32; o <<= 1) {
            float n = __shfl_up_sync(0xffffffffu, p, o);
            if (lane >= o) p = fmaxf(p, n);
        }
        if (lane == 31) wmax[wid] = p;
        __syncthreads();
        if (tid < 8) {
            float q = wmax[tid];
#pragma unroll
            for (int o = 1; o < 8; o <<= 1) {
                float n = __shfl_up_sync(0xffu, q, o);
                if (tid >= o) q = fmaxf(q, n);
            }
            wmax[tid] = q;
        }
        __syncthreads();
        if (wid > 0) p = fmaxf(p, wmax[wid - 1]);

        // rmax at this frame, then Wiener gain g = m^2/(m^2 + max(0.5*rmax^2,1e-8))
        float rm = dpow * fmaxf(DECAY * carry, p);
        if (f < NF) {
            float a = m * m;
            float b = fmaxf(0.5f * rm * rm, 1e-8f);
            g_gain[(size_t)f * NK + k] = a / (a + b);
        }

        // carry = rmax at t=255 of this chunk (last chunk's carry unused)
        if (tid == 255) sh_carry = rm;
        __syncthreads();
        carry = sh_carry;
    }
}

// ---------------- kernel 3: ISTFT + overlap-add --------------------------
__global__ void istft_kernel()
{
    __shared__ float2 sh[512];
    __shared__ float2 G[257];
    int f   = blockIdx.x;
    int tid = threadIdx.x;
    size_t base = (size_t)f * NK;

    {
        float2 s = g_spec[base + tid];
        float  g = g_gain[base + tid];
        G[tid] = make_float2(s.x * g, s.y * g);
        if (tid == 0) {
            float2 s1 = g_spec[base + 256];
            float  g1 = g_gain[base + 256];
            G[256] = make_float2(s1.x * g1, s1.y * g1);
        }
    }
    __syncthreads();

    // build full conjugate-symmetric 512-bin spectrum in bit-reversed order
    {
        float2 v0 = G[tid];
        sh[__brev((unsigned)tid) >> 23] = v0;
        int k2 = tid + 256;
        float2 v2;
        if (k2 == 256) v2 = G[256];
        else { float2 gg = G[512 - k2]; v2 = make_float2(gg.x, -gg.y); }
        sh[__brev((unsigned)k2) >> 23] = v2;
    }
    __syncthreads();

    fft512_stages(sh, tid, +1.0f);       // inverse (unscaled)

    const float scale = 1.0f / 512.0f;
    long start = (long)f * HOP;
#pragma unroll
    for (int r = 0; r < 2; r++) {
        int j = tid + r * 256;
        float val = sh[j].x * scale * hann_win(j);
        atomicAdd(&g_y[start + j], val);
    }
}

// ---------------- kernel 4: normalize by window-sum and trim -------------
__global__ void finalize_kernel(float* __restrict__ out)
{
    int i = blockIdx.x * blockDim.x + threadIdx.x;
    if (i >= TLEN) return;
    int t = i + PAD;
    float ws = 0.0f;
    int ftop = t >> 7;                   // t / HOP
#pragma unroll
    for (int j = 0; j < 4; j++) {
        int f = ftop - j;
        if (f < 0 || f >= NF) continue;
        int o = t - (f << 7);            // in [0, 512)
        float w = hann_win(o);
        ws += w * w;
    }
    out[i] = g_y[t] / fmaxf(ws, 1e-11f);
}

// ---------------- launch --------------------------------------------------
extern "C" void kernel_launch(void* const* d_in, const int* in_sizes, int n_in,
                              void* d_out, int out_size)
{
    const float* x   = (const float*)d_in[0];
    float*       out = (float*)d_out;

    zero_y_kernel<<<(XP + 1023) / 1024, 1024>>>();
    stft_kernel<<<NF, 256>>>(x);
    scan_kernel<<<NK, 256>>>();
    istft_kernel<<<NF, 256>>>();
    finalize_kernel<<<(TLEN + 255) / 256, 256>>>(out);
}

// round 2
// speedup vs baseline: 1.1110x; 1.1110x over previous
#include <cuda_runtime.h>
#include <math.h>

#define TLEN 8388608
#define NFFT 512
#define HOP  128
#define NK   257
#define NF   65537
#define XP   (TLEN + NFFT)   /* 8389120 padded length */
#define PAD  256

// ---------------- device scratch (no allocations allowed) ----------------
__device__ float2 g_spec[(size_t)NF * NK];   // complex STFT, [frame][bin]
__device__ float  g_gain[(size_t)NF * NK];   // Wiener gain,  [frame][bin]
__device__ float  g_y[XP];                   // overlap-add accumulator

__device__ __forceinline__ int brev8(int j) { return (int)(__brev((unsigned)j) >> 24); }

// reflect-padded input load (pad = 256 both sides)
__device__ __forceinline__ float xload(const float* __restrict__ x, long gi)
{
    long i = gi - PAD;
    if (i < 0)     i = -i;
    if (i >= TLEN) i = 2L * TLEN - 2 - i;
    return x[i];
}

// Hann window from twiddle table: win(j) = 0.5*(1 - cos(2*pi*j/512)),
// cos(2*pi*j/512) = tw[j].x for j<256, = -tw[j-256].x for j>=256.
__device__ __forceinline__ float win_tab(const float2* tw, int j)
{
    float c = (j < 256) ? tw[j].x : -tw[j - 256].x;
    return 0.5f * (1.0f - c);
}

// 256-pt in-place complex radix-2 DIT FFT, 128 threads, input bit-reversed.
// tw[j] = exp(-2*pi*i*j/512); stage twiddle = tw[pos << (9-l)].
// fwd=true: W = tw (e^{-i}), fwd=false: conjugate (e^{+i}).
template <bool FWD>
__device__ __forceinline__ void fft256(float2* sh, const float2* tw, int t)
{
#pragma unroll
    for (int l = 1; l <= 8; l++) {
        int half = 1 << (l - 1);
        int pos  = t & (half - 1);
        int i0   = ((t >> (l - 1)) << l) + pos;
        int i1   = i0 + half;
        float2 w = tw[pos << (9 - l)];
        float wy = FWD ? w.y : -w.y;
        float2 u = sh[i0], v = sh[i1];
        float tr = v.x * w.x - v.y * wy;
        float ti = v.x * wy + v.y * w.x;
        sh[i0] = make_float2(u.x + tr, u.y + ti);
        sh[i1] = make_float2(u.x - tr, u.y - ti);
        __syncthreads();
    }
}

// ---------------- kernel 0: zero the OLA accumulator ---------------------
__global__ void zero_y_kernel()
{
    int i = blockIdx.x * blockDim.x + threadIdx.x;
    if (i < XP) g_y[i] = 0.0f;
}

// ---------------- kernel 1: STFT (packed real->half-size complex) --------
// one block (128 threads) per frame.
__global__ void stft_kernel(const float* __restrict__ x)
{
    __shared__ float2 tw[256];
    __shared__ float2 sh[256];
    int f = blockIdx.x;
    int t = threadIdx.x;          // 0..127

    // twiddle table: tw[j] = exp(-2*pi*i*j/512)
#pragma unroll
    for (int r = 0; r < 2; r++) {
        int j = t + r * 128;
        float s, c;
        sincospif((float)j * (1.0f / 256.0f), &s, &c);
        tw[j] = make_float2(c, -s);
    }
    __syncthreads();

    long start = (long)f * HOP;

    // load + window + pack: z[n] = v(2n) + i*v(2n+1), n = t and t+128
#pragma unroll
    for (int r = 0; r < 2; r++) {
        int n  = t + r * 128;
        int j0 = 2 * n, j1 = 2 * n + 1;
        float a = xload(x, start + j0) * win_tab(tw, j0);
        float b = xload(x, start + j1) * win_tab(tw, j1);
        sh[brev8(n)] = make_float2(a, b);
    }
    __syncthreads();

    fft256<true>(sh, tw, t);      // forward; ends with syncthreads

    // unpack Z -> X[0..256]
    size_t base = (size_t)f * NK;
    float2 z0 = sh[0];
#pragma unroll
    for (int r = 0; r < 2; r++) {
        int k = t + r * 128;
        float2 X;
        if (k == 0) {
            X = make_float2(z0.x + z0.y, 0.0f);
        } else {
            float2 Zk = sh[k], Zm = sh[256 - k];
            float2 Xe = make_float2(0.5f * (Zk.x + Zm.x), 0.5f * (Zk.y - Zm.y));
            float2 d  = make_float2(0.5f * (Zk.x - Zm.x), 0.5f * (Zk.y + Zm.y));
            float2 Xo = make_float2(d.y, -d.x);          // -i * d
            float2 w  = tw[k];                            // W_512^k
            X = make_float2(Xe.x + (Xo.x * w.x - Xo.y * w.y),
                            Xe.y + (Xo.x * w.y + Xo.y * w.x));
        }
        g_spec[base + k] = X;
    }
    if (t == 0) g_spec[base + 256] = make_float2(z0.x - z0.y, 0.0f);
}

// ---------------- kernel 2: running-max scan + Wiener gain ---------------
// one block per frequency bin k; chunked parallel max-scan over frames.
// rmax_t = d^t * prefmax_s( m_s * d^{-s} ), chunk-rescaled to stay in range.
__global__ void scan_kernel()
{
    const int k    = blockIdx.x;         // 0..256
    const int tid  = threadIdx.x;        // 0..255
    const int lane = tid & 31;
    const int wid  = tid >> 5;

    __shared__ float wmax[8];
    __shared__ float sh_carry;

    const float LND   = 1.0005003335835335e-3f;  // -ln(0.999)
    const float DECAY = 0.999f;
    const float dinv  = expf((float)tid * LND);  // d^{-tid}
    const float dpow  = expf(-(float)tid * LND); // d^{+tid}

    float carry = 0.0f;
    const int NCH = (NF + 255) / 256;    // 257 chunks

    float2 s_cur = make_float2(0.f, 0.f);
    if (tid < NF) s_cur = g_spec[(size_t)tid * NK + k];

    for (int c = 0; c < NCH; c++) {
        int f = c * 256 + tid;
        float m = 0.0f, v = 0.0f;
        if (f < NF) {
            m = sqrtf(s_cur.x * s_cur.x + s_cur.y * s_cur.y);
            v = m * dinv;
        }
        if (c + 1 < NCH) {
            int fn = (c + 1) * 256 + tid;
            if (fn < NF) s_cur = g_spec[(size_t)fn * NK + k];
        }

        float p = v;
#pragma unroll
        for (int o = 1; o < 32; o <<= 1) {
            float n = __shfl_up_sync(0xffffffffu, p, o);
            if (lane >= o) p = fmaxf(p, n);
        }
        if (lane == 31) wmax[wid] = p;
        __syncthreads();
        if (tid < 8) {
            float q = wmax[tid];
#pragma unroll
            for (int o = 1; o < 8; o <<= 1) {
                float n = __shfl_up_sync(0xffu, q, o);
                if (tid >= o) q = fmaxf(q, n);
            }
            wmax[tid] = q;
        }
        __syncthreads();
        if (wid > 0) p = fmaxf(p, wmax[wid - 1]);

        float rm = dpow * fmaxf(DECAY * carry, p);
        if (f < NF) {
            float a = m * m;
            float b = fmaxf(0.5f * rm * rm, 1e-8f);
            g_gain[(size_t)f * NK + k] = a / (a + b);
        }

        if (tid == 255) sh_carry = rm;
        __syncthreads();
        carry = sh_carry;
    }
}

// ---------------- kernel 3: ISTFT (half-size complex) + overlap-add ------
__global__ void istft_kernel()
{
    __shared__ float2 tw[256];
    __shared__ float2 sh[256];
    __shared__ float2 Xs[257];
    int f = blockIdx.x;
    int t = threadIdx.x;          // 0..127
    size_t base = (size_t)f * NK;

#pragma unroll
    for (int r = 0; r < 2; r++) {
        int j = t + r * 128;
        float s, c;
        sincospif((float)j * (1.0f / 256.0f), &s, &c);
        tw[j] = make_float2(c, -s);
    }

    // load enhanced spectrum X[k] = gain * spec
#pragma unroll
    for (int r = 0; r < 2; r++) {
        int k = t + r * 128;
        float2 s = g_spec[base + k];
        float  g = g_gain[base + k];
        Xs[k] = make_float2(s.x * g, s.y * g);
    }
    if (t == 0) {
        float2 s = g_spec[base + 256];
        float  g = g_gain[base + 256];
        Xs[256] = make_float2(s.x * g, s.y * g);
    }
    __syncthreads();

    // pack: Z[k] = Xe[k] + i*Xo[k], k = 0..255
#pragma unroll
    for (int r = 0; r < 2; r++) {
        int k = t + r * 128;
        float2 Xk = Xs[k], Xm = Xs[256 - k];
        float2 Xe = make_float2(0.5f * (Xk.x + Xm.x), 0.5f * (Xk.y - Xm.y));
        float2 hd = make_float2(0.5f * (Xk.x - Xm.x), 0.5f * (Xk.y + Xm.y));
        float2 w  = tw[k];                      // W^{-k} = conj(tw[k])
        float2 Xo = make_float2(hd.x * w.x + hd.y * w.y,
                                hd.y * w.x - hd.x * w.y);
        sh[brev8(k)] = make_float2(Xe.x - Xo.y, Xe.y + Xo.x);
    }
    __syncthreads();

    fft256<false>(sh, tw, t);     // inverse (unnormalized); ends with sync

    const float sc = 1.0f / 256.0f;
    long start = (long)f * HOP;
#pragma unroll
    for (int r = 0; r < 2; r++) {
        int n  = t + r * 128;
        float2 z = sh[n];
        int j0 = 2 * n, j1 = 2 * n + 1;
        atomicAdd(&g_y[start + j0], z.x * sc * win_tab(tw, j0));
        atomicAdd(&g_y[start + j1], z.y * sc * win_tab(tw, j1));
    }
}

// ---------------- kernel 4: normalize by window-sum and trim -------------
__global__ void finalize_kernel(float* __restrict__ out)
{
    int i = blockIdx.x * blockDim.x + threadIdx.x;
    if (i >= TLEN) return;
    int t = i + PAD;
    float ws = 0.0f;
    int ftop = t >> 7;                   // t / HOP
#pragma unroll
    for (int j = 0; j < 4; j++) {
        int f = ftop - j;
        if (f < 0 || f >= NF) continue;
        int o = t - (f << 7);            // in [0, 512)
        float s, c;
        sincospif((float)o * (1.0f / 256.0f), &s, &c);
        float w = 0.5f * (1.0f - c);
        ws += w * w;
    }
    out[i] = g_y[t] / fmaxf(ws, 1e-11f);
}

// ---------------- launch --------------------------------------------------
extern "C" void kernel_launch(void* const* d_in, const int* in_sizes, int n_in,
                              void* d_out, int out_size)
{
    const float* x   = (const float*)d_in[0];
    float*       out = (float*)d_out;

    zero_y_kernel<<<(XP + 1023) / 1024, 1024>>>();
    stft_kernel<<<NF, 128>>>(x);
    scan_kernel<<<NK, 256>>>();
    istft_kernel<<<NF, 128>>>();
    finalize_kernel<<<(TLEN + 255) / 256, 256>>>(out);
}

// round 4
// speedup vs baseline: 1.1140x; 1.0027x over previous
#include <cuda_runtime.h>
#include <math.h>

#define TLEN 8388608
#define NFFT 512
#define HOP  128
#define NK   257
#define NF   65537
#define XP   (TLEN + NFFT)   /* 8389120 padded length */
#define PAD  256

// ---------------- device scratch (no allocations allowed) ----------------
__device__ float2 g_spec[(size_t)NF * NK];   // complex STFT, [frame][bin]
__device__ float  g_gain[(size_t)NF * NK];   // Wiener gain,  [frame][bin]
__device__ float  g_y[XP];                   // overlap-add accumulator

__device__ __forceinline__ int brev8(int j) { return (int)(__brev((unsigned)j) >> 24); }

// reflect-padded input load (pad = 256 both sides)
__device__ __forceinline__ float xload(const float* __restrict__ x, long gi)
{
    long i = gi - PAD;
    if (i < 0)     i = -i;
    if (i >= TLEN) i = 2L * TLEN - 2 - i;
    return x[i];
}

// Hann window from twiddle table: win(j) = 0.5*(1 - cos(2*pi*j/512)),
// cos(2*pi*j/512) = tw[j].x for j<256, = -tw[j-256].x for j>=256.
__device__ __forceinline__ float win_tab(const float2* tw, int j)
{
    float c = (j < 256) ? tw[j].x : -tw[j - 256].x;
    return 0.5f * (1.0f - c);
}

// 256-pt in-place complex radix-2 DIT FFT, 128 threads, input bit-reversed.
// tw[j] = exp(-2*pi*i*j/512); stage twiddle = tw[pos << (9-l)].
// fwd=true: W = tw (e^{-i}), fwd=false: conjugate (e^{+i}).
template <bool FWD>
__device__ __forceinline__ void fft256(float2* sh, const float2* tw, int t)
{
#pragma unroll
    for (int l = 1; l <= 8; l++) {
        int half = 1 << (l - 1);
        int pos  = t & (half - 1);
        int i0   = ((t >> (l - 1)) << l) + pos;
        int i1   = i0 + half;
        float2 w = tw[pos << (9 - l)];
        float wy = FWD ? w.y : -w.y;
        float2 u = sh[i0], v = sh[i1];
        float tr = v.x * w.x - v.y * wy;
        float ti = v.x * wy + v.y * w.x;
        sh[i0] = make_float2(u.x + tr, u.y + ti);
        sh[i1] = make_float2(u.x - tr, u.y - ti);
        __syncthreads();
    }
}

// ---------------- kernel 0: zero the OLA accumulator ---------------------
__global__ void zero_y_kernel()
{
    int i = blockIdx.x * blockDim.x + threadIdx.x;
    if (i < XP) g_y[i] = 0.0f;
}

// ---------------- kernel 1: STFT (packed real->half-size complex) --------
// one block (128 threads) per frame.
__global__ void stft_kernel(const float* __restrict__ x)
{
    __shared__ float2 tw[256];
    __shared__ float2 sh[256];
    int f = blockIdx.x;
    int t = threadIdx.x;          // 0..127

    // twiddle table: tw[j] = exp(-2*pi*i*j/512)
#pragma unroll
    for (int r = 0; r < 2; r++) {
        int j = t + r * 128;
        float s, c;
        sincospif((float)j * (1.0f / 256.0f), &s, &c);
        tw[j] = make_float2(c, -s);
    }
    __syncthreads();

    long start = (long)f * HOP;

    // load + window + pack: z[n] = v(2n) + i*v(2n+1), n = t and t+128
#pragma unroll
    for (int r = 0; r < 2; r++) {
        int n  = t + r * 128;
        int j0 = 2 * n, j1 = 2 * n + 1;
        float a = xload(x, start + j0) * win_tab(tw, j0);
        float b = xload(x, start + j1) * win_tab(tw, j1);
        sh[brev8(n)] = make_float2(a, b);
    }
    __syncthreads();

    fft256<true>(sh, tw, t);      // forward; ends with syncthreads

    // unpack Z -> X[0..256]
    size_t base = (size_t)f * NK;
    float2 z0 = sh[0];
#pragma unroll
    for (int r = 0; r < 2; r++) {
        int k = t + r * 128;
        float2 X;
        if (k == 0) {
            X = make_float2(z0.x + z0.y, 0.0f);
        } else {
            float2 Zk = sh[k], Zm = sh[256 - k];
            float2 Xe = make_float2(0.5f * (Zk.x + Zm.x), 0.5f * (Zk.y - Zm.y));
            float2 d  = make_float2(0.5f * (Zk.x - Zm.x), 0.5f * (Zk.y + Zm.y));
            float2 Xo = make_float2(d.y, -d.x);          // -i * d
            float2 w  = tw[k];                            // W_512^k
            X = make_float2(Xe.x + (Xo.x * w.x - Xo.y * w.y),
                            Xe.y + (Xo.x * w.y + Xo.y * w.x));
        }
        g_spec[base + k] = X;
    }
    if (t == 0) g_spec[base + 256] = make_float2(z0.x - z0.y, 0.0f);
}

// ---------------- kernel 2: running-max scan + Wiener gain ---------------
// one block per frequency bin k; chunked parallel max-scan over frames.
// rmax_t = d^t * prefmax_s( m_s * d^{-s} ), chunk-rescaled to stay in range.
__global__ void scan_kernel()
{
    const int k    = blockIdx.x;         // 0..256
    const int tid  = threadIdx.x;        // 0..255
    const int lane = tid & 31;
    const int wid  = tid >> 5;

    __shared__ float wmax[8];
    __shared__ float sh_carry;

    const float LND   = 1.0005003335835335e-3f;  // -ln(0.999)
    const float DECAY = 0.999f;
    const float dinv  = expf((float)tid * LND);  // d^{-tid}
    const float dpow  = expf(-(float)tid * LND); // d^{+tid}

    float carry = 0.0f;
    const int NCH = (NF + 255) / 256;    // 257 chunks

    float2 s_cur = make_float2(0.f, 0.f);
    if (tid < NF) s_cur = g_spec[(size_t)tid * NK + k];

    for (int c = 0; c < NCH; c++) {
        int f = c * 256 + tid;
        float m = 0.0f, v = 0.0f;
        if (f < NF) {
            m = sqrtf(s_cur.x * s_cur.x + s_cur.y * s_cur.y);
            v = m * dinv;
        }
        if (c + 1 < NCH) {
            int fn = (c + 1) * 256 + tid;
            if (fn < NF) s_cur = g_spec[(size_t)fn * NK + k];
        }

        float p = v;
#pragma unroll
        for (int o = 1; o < 32; o <<= 1) {
            float n = __shfl_up_sync(0xffffffffu, p, o);
            if (lane >= o) p = fmaxf(p, n);
        }
        if (lane == 31) wmax[wid] = p;
        __syncthreads();
        if (tid < 8) {
            float q = wmax[tid];
#pragma unroll
            for (int o = 1; o < 8; o <<= 1) {
                float n = __shfl_up_sync(0xffu, q, o);
                if (tid >= o) q = fmaxf(q, n);
            }
            wmax[tid] = q;
        }
        __syncthreads();
        if (wid > 0) p = fmaxf(p, wmax[wid - 1]);

        float rm = dpow * fmaxf(DECAY * carry, p);
        if (f < NF) {
            float a = m * m;
            float b = fmaxf(0.5f * rm * rm, 1e-8f);
            g_gain[(size_t)f * NK + k] = a / (a + b);
        }

        if (tid == 255) sh_carry = rm;
        __syncthreads();
        carry = sh_carry;
    }
}

// ---------------- kernel 3: ISTFT (half-size complex) + overlap-add ------
__global__ void istft_kernel()
{
    __shared__ float2 tw[256];
    __shared__ float2 sh[256];
    __shared__ float2 Xs[257];
    int f = blockIdx.x;
    int t = threadIdx.x;          // 0..127
    size_t base = (size_t)f * NK;

#pragma unroll
    for (int r = 0; r < 2; r++) {
        int j = t + r * 128;
        float s, c;
        sincospif((float)j * (1.0f / 256.0f), &s, &c);
        tw[j] = make_float2(c, -s);
    }

    // load enhanced spectrum X[k] = gain * spec
#pragma unroll
    for (int r = 0; r < 2; r++) {
        int k = t + r * 128;
        float2 s = g_spec[base + k];
        float  g = g_gain[base + k];
        Xs[k] = make_float2(s.x * g, s.y * g);
    }
    if (t == 0) {
        float2 s = g_spec[base + 256];
        float  g = g_gain[base + 256];
        Xs[256] = make_float2(s.x * g, s.y * g);
    }
    __syncthreads();

    // pack: Z[k] = Xe[k] + i*Xo[k], k = 0..255
#pragma unroll
    for (int r = 0; r < 2; r++) {
        int k = t + r * 128;
        float2 Xk = Xs[k], Xm = Xs[256 - k];
        float2 Xe = make_float2(0.5f * (Xk.x + Xm.x), 0.5f * (Xk.y - Xm.y));
        float2 hd = make_float2(0.5f * (Xk.x - Xm.x), 0.5f * (Xk.y + Xm.y));
        float2 w  = tw[k];                      // W^{-k} = conj(tw[k])
        float2 Xo = make_float2(hd.x * w.x + hd.y * w.y,
                                hd.y * w.x - hd.x * w.y);
        sh[brev8(k)] = make_float2(Xe.x - Xo.y, Xe.y + Xo.x);
    }
    __syncthreads();

    fft256<false>(sh, tw, t);     // inverse (unnormalized); ends with sync

    const float sc = 1.0f / 256.0f;
    long start = (long)f * HOP;
#pragma unroll
    for (int r = 0; r < 2; r++) {
        int n  = t + r * 128;
        float2 z = sh[n];
        int j0 = 2 * n, j1 = 2 * n + 1;
        atomicAdd(&g_y[start + j0], z.x * sc * win_tab(tw, j0));
        atomicAdd(&g_y[start + j1], z.y * sc * win_tab(tw, j1));
    }
}

// ---------------- kernel 4: normalize by window-sum and trim -------------
__global__ void finalize_kernel(float* __restrict__ out)
{
    int i = blockIdx.x * blockDim.x + threadIdx.x;
    if (i >= TLEN) return;
    int t = i + PAD;
    float ws = 0.0f;
    int ftop = t >> 7;                   // t / HOP
#pragma unroll
    for (int j = 0; j < 4; j++) {
        int f = ftop - j;
        if (f < 0 || f >= NF) continue;
        int o = t - (f << 7);            // in [0, 512)
        float s, c;
        sincospif((float)o * (1.0f / 256.0f), &s, &c);
        float w = 0.5f * (1.0f - c);
        ws += w * w;
    }
    out[i] = g_y[t] / fmaxf(ws, 1e-11f);
}

// ---------------- launch --------------------------------------------------
extern "C" void kernel_launch(void* const* d_in, const int* in_sizes, int n_in,
                              void* d_out, int out_size)
{
    const float* x   = (const float*)d_in[0];
    float*       out = (float*)d_out;

    zero_y_kernel<<<(XP + 1023) / 1024, 1024>>>();
    stft_kernel<<<NF, 128>>>(x);
    scan_kernel<<<NK, 256>>>();
    istft_kernel<<<NF, 128>>>();
    finalize_kernel<<<(TLEN + 255) / 256, 256>>>(out);
}